// round 14
// baseline (speedup 1.0000x reference)
#include <cuda_runtime.h>
#include <cuda_fp16.h>
#include <cstdint>

// ---------------- problem constants ----------------
#define BATCH   8
#define SEQ     4096
#define DMODEL  1024
#define MTOT    (BATCH * SEQ)      // 32768
#define KTOT    DMODEL             // 1024
#define NTOT    (2 * DMODEL)       // 2048 fused (decay | input)

// ---------------- GEMM tiling ----------------
#define M_TILE   256
#define N_TILE   128
#define K_CHUNK  64
#define N_CHUNKS (KTOT / K_CHUNK)   // 16
#define GTHREADS 256
#define NSTAGE   3

// smem: padded pitch 72 fp16 (144 B) -> conflict-free ldmatrix (144%128=16)
#define PITCH 72
#define A_TILE_BYTES (M_TILE * PITCH * 2)     // 36864
#define B_TILE_BYTES (N_TILE * PITCH * 2)     // 18432
#define OFF_A 0
#define OFF_B A_TILE_BYTES
#define STAGE_BYTES (A_TILE_BYTES + B_TILE_BYTES)  // 55296
#define SMEM_TOTAL  (NSTAGE * STAGE_BYTES)         // 165888

// ---------------- scan segmentation ----------------
#define NSEG   16
#define SEGLEN (SEQ / NSEG)         // 256

// ---------------- device scratch ----------------
__device__ __half X_hi[(size_t)MTOT * KTOT];
__device__ __half Wf_hi[(size_t)NTOT * KTOT];
__device__ float g_decays[(size_t)MTOT * DMODEL];
__device__ float g_inj[(size_t)MTOT * DMODEL];
__device__ float g_segA[BATCH * NSEG * DMODEL];
__device__ float g_segB[BATCH * NSEG * DMODEL];
__device__ float g_segInit[BATCH * NSEG * DMODEL];

// ---------------- PTX helpers ----------------
__device__ __forceinline__ uint32_t s2u(const void* p) {
    return (uint32_t)__cvta_generic_to_shared(p);
}

#define CPA16(s, g) asm volatile("cp.async.cg.shared.global [%0], [%1], 16;" :: "r"(s), "l"(g) : "memory")
#define CPA_COMMIT() asm volatile("cp.async.commit_group;" ::: "memory")
#define CPA_WAIT1()  asm volatile("cp.async.wait_group 1;" ::: "memory")
#define CPA_WAIT0()  asm volatile("cp.async.wait_group 0;" ::: "memory")

__device__ __forceinline__ void ldsm_x4(uint32_t addr, uint32_t& r0, uint32_t& r1,
                                        uint32_t& r2, uint32_t& r3) {
    asm volatile("ldmatrix.sync.aligned.m8n8.x4.shared.b16 {%0,%1,%2,%3}, [%4];"
                 : "=r"(r0), "=r"(r1), "=r"(r2), "=r"(r3) : "r"(addr));
}

// fp16 inputs, fp32 accumulate
__device__ __forceinline__ void mma_f32(float* c, const uint32_t* a,
                                        uint32_t b0, uint32_t b1) {
    asm volatile(
        "mma.sync.aligned.m16n8k16.row.col.f32.f16.f16.f32 "
        "{%0,%1,%2,%3}, {%4,%5,%6,%7}, {%8,%9}, {%0,%1,%2,%3};"
        : "+f"(c[0]), "+f"(c[1]), "+f"(c[2]), "+f"(c[3])
        : "r"(a[0]), "r"(a[1]), "r"(a[2]), "r"(a[3]), "r"(b0), "r"(b1));
}

// ---------------- ncu alignment no-op (keeps gemm in profiled launch slot) ----
__global__ void prof_align_kernel() {}

__global__ __launch_bounds__(256)
void convert_x_kernel(const float* __restrict__ x) {
    size_t i = (size_t)blockIdx.x * 256 + threadIdx.x;      // float4 index
    float4 v = reinterpret_cast<const float4*>(x)[i];
    __half2 uh0 = __halves2half2(__float2half_rn(v.x), __float2half_rn(v.y));
    __half2 uh1 = __halves2half2(__float2half_rn(v.z), __float2half_rn(v.w));
    reinterpret_cast<__half2*>(X_hi)[2 * i]     = uh0;
    reinterpret_cast<__half2*>(X_hi)[2 * i + 1] = uh1;
}

__global__ __launch_bounds__(256)
void convert_w_kernel(const float* __restrict__ Wd, const float* __restrict__ Wi) {
    size_t i = (size_t)blockIdx.x * 256 + threadIdx.x;      // float4 index, 524288
    int row = (int)(i >> 8);
    int c4  = (int)(i & 255);
    const float* src = (row < DMODEL) ? (Wd + (size_t)row * KTOT)
                                      : (Wi + (size_t)(row - DMODEL) * KTOT);
    float4 v = reinterpret_cast<const float4*>(src)[c4];
    __half2 uh0 = __halves2half2(__float2half_rn(v.x), __float2half_rn(v.y));
    __half2 uh1 = __halves2half2(__float2half_rn(v.z), __float2half_rn(v.w));
    reinterpret_cast<__half2*>(Wf_hi)[2 * i]     = uh0;
    reinterpret_cast<__half2*>(Wf_hi)[2 * i + 1] = uh1;
}

// ---------------- GEMM: load one K64-chunk into a stage ----------------
// 256 threads: A = 256 rows x 8 16B-chunks = 2048 transfers (8 iters);
//              B = 128 rows x 8 = 1024 (4 iters).
__device__ __forceinline__ void load_chunk(uint32_t smem_u, int c, int st,
                                           int m0, int n0, int tid) {
    const int k0 = c * K_CHUNK;
    const uint32_t base = smem_u + st * STAGE_BYTES;
#pragma unroll
    for (int it = 0; it < 8; ++it) {
        int idx = it * 256 + tid;
        int row = idx >> 3;
        int kk  = (idx & 7) * 8;
        uint32_t so = (uint32_t)(row * PITCH + kk) * 2;
        size_t gA = (size_t)(m0 + row) * KTOT + k0 + kk;
        CPA16(base + OFF_A + so, X_hi + gA);
    }
#pragma unroll
    for (int it = 0; it < 4; ++it) {
        int idx = it * 256 + tid;
        int row = idx >> 3;
        int kk  = (idx & 7) * 8;
        uint32_t so = (uint32_t)(row * PITCH + kk) * 2;
        size_t gB = (size_t)(n0 + row) * KTOT + k0 + kk;
        CPA16(base + OFF_B + so, Wf_hi + gB);
    }
}

// ---------------- GEMM + gate epilogue (single-pass fp16, fp32 accum) ---------
// 8 warps: 4(m) x 2(n); warp tile 64x64; K64 chunks with 4 kh-phases,
// intra-chunk fragment double-buffer; loads issued post-barrier (NSTAGE=3).
__global__ __launch_bounds__(GTHREADS, 1)
void gemm_tc_kernel(const float* __restrict__ bd, const float* __restrict__ bi) {
    extern __shared__ char smem[];
    const uint32_t smem_u = s2u(smem);
    const int tid = threadIdx.x;
    const int wid = tid >> 5;
    const int lane = tid & 31;

    const int n0 = blockIdx.x * N_TILE;        // 0..1920
    const int m0 = blockIdx.y * M_TILE;
    const bool is_decay = (n0 < DMODEL);
    const int colbase = is_decay ? n0 : (n0 - DMODEL);
    const float* bv = is_decay ? bd : bi;

    const int warp_m = (wid & 3) * 64;         // 4 warps along M (64 rows)
    const int warp_n = (wid >> 2) * 64;        // 2 warps along N (64 cols)

    float acc[4][8][4];
#pragma unroll
    for (int mt = 0; mt < 4; ++mt)
#pragma unroll
        for (int nt = 0; nt < 8; ++nt)
#pragma unroll
            for (int q = 0; q < 4; ++q) acc[mt][nt][q] = 0.0f;

    // ldmatrix lane addressing
    const int a_r = lane & 15;
    const int a_c = (lane >> 4) * 8;
    const int b_quad = lane >> 3;
    const int b_r = lane & 7;
    const int b_row_off = ((b_quad >> 1) * 8) + b_r;
    const int b_k_off = (b_quad & 1) * 8;

    uint32_t ah[2][4][4];                      // [buf][mt][reg]
    uint32_t bh[2][4][4];                      // [buf][ng][reg]

#define LOAD_FRAGS(buf, base, kc)                                              \
    do {                                                                       \
        _Pragma("unroll")                                                      \
        for (int mt = 0; mt < 4; ++mt) {                                       \
            uint32_t off = (uint32_t)((warp_m + mt * 16 + a_r) * PITCH + (kc) + a_c) * 2; \
            ldsm_x4((base) + OFF_A + off, ah[buf][mt][0], ah[buf][mt][1],      \
                    ah[buf][mt][2], ah[buf][mt][3]);                           \
        }                                                                      \
        _Pragma("unroll")                                                      \
        for (int ng = 0; ng < 4; ++ng) {                                       \
            uint32_t off = (uint32_t)((warp_n + ng * 16 + b_row_off) * PITCH + (kc) + b_k_off) * 2; \
            ldsm_x4((base) + OFF_B + off, bh[buf][ng][0], bh[buf][ng][1],      \
                    bh[buf][ng][2], bh[buf][ng][3]);                           \
        }                                                                      \
    } while (0)

#define MMA_FRAGS(buf)                                                         \
    do {                                                                       \
        _Pragma("unroll")                                                      \
        for (int ng = 0; ng < 4; ++ng)                                         \
            _Pragma("unroll")                                                  \
            for (int mt = 0; mt < 4; ++mt) {                                   \
                mma_f32(acc[mt][2 * ng + 0], ah[buf][mt], bh[buf][ng][0], bh[buf][ng][1]); \
                mma_f32(acc[mt][2 * ng + 1], ah[buf][mt], bh[buf][ng][2], bh[buf][ng][3]); \
            }                                                                  \
    } while (0)

    // prologue: 2 chunk-loads in flight
    load_chunk(smem_u, 0, 0, m0, n0, tid); CPA_COMMIT();
    load_chunk(smem_u, 1, 1, m0, n0, tid); CPA_COMMIT();

    int st = 0;                                // = c % NSTAGE
    for (int c = 0; c < N_CHUNKS; ++c) {
        // ensure chunk c resident (c+1 may still be in flight)
        if (c < N_CHUNKS - 1) { CPA_WAIT1(); } else { CPA_WAIT0(); }
        __syncthreads();
        // issue chunk c+2 into stage (c+2)%3 — safe post-barrier: that stage
        // was last read in iteration c-1, which every warp has now left.
        if (c + 2 < N_CHUNKS) {
            int wst = st + 2; if (wst >= NSTAGE) wst -= NSTAGE;
            load_chunk(smem_u, c + 2, wst, m0, n0, tid);
            CPA_COMMIT();
        }

        const uint32_t base = smem_u + st * STAGE_BYTES;
        // 4 kh-phases, fragment double-buffer: L0;(L1|M0);(L2|M1);(L3|M2);M3
        LOAD_FRAGS(0, base, 0);
        LOAD_FRAGS(1, base, 16);
        MMA_FRAGS(0);
        LOAD_FRAGS(0, base, 32);
        MMA_FRAGS(1);
        LOAD_FRAGS(1, base, 48);
        MMA_FRAGS(0);
        MMA_FRAGS(1);

        ++st; if (st == NSTAGE) st = 0;
    }

    // ---- epilogue: bias (+sigmoid), float2 stores ----
    float* dst = is_decay ? g_decays : g_inj;
#pragma unroll
    for (int mt = 0; mt < 4; ++mt) {
        int row0 = m0 + warp_m + mt * 16 + (lane >> 2);
#pragma unroll
        for (int nt = 0; nt < 8; ++nt) {
            int gcol = colbase + warp_n + nt * 8 + (lane & 3) * 2;
            float2 bias2 = *reinterpret_cast<const float2*>(bv + gcol);
            float v0 = acc[mt][nt][0] + bias2.x;
            float v1 = acc[mt][nt][1] + bias2.y;
            float v2 = acc[mt][nt][2] + bias2.x;
            float v3 = acc[mt][nt][3] + bias2.y;
            if (is_decay) {
                v0 = __fdividef(1.0f, 1.0f + __expf(-v0));
                v1 = __fdividef(1.0f, 1.0f + __expf(-v1));
                v2 = __fdividef(1.0f, 1.0f + __expf(-v2));
                v3 = __fdividef(1.0f, 1.0f + __expf(-v3));
            }
            *reinterpret_cast<float2*>(dst + (size_t)row0 * DMODEL + gcol) =
                make_float2(v0, v1);
            *reinterpret_cast<float2*>(dst + (size_t)(row0 + 8) * DMODEL + gcol) =
                make_float2(v2, v3);
        }
    }
#undef LOAD_FRAGS
#undef MMA_FRAGS
}

// ---------------- segmented scan ----------------
__global__ __launch_bounds__(256)
void scan_pass1() {
    const int g = blockIdx.x * 256 + threadIdx.x;      // 0..131071
    const int e = g & (DMODEL - 1);
    const int bs = g >> 10;
    const int seg = bs & (NSEG - 1);
    const int b = bs >> 4;
    size_t p = ((size_t)b * SEQ + (size_t)seg * SEGLEN) * DMODEL + e;

    float s = 0.0f, A = 1.0f;
    for (int t = 0; t < SEGLEN; t += 8) {
        float d[8], v[8];
#pragma unroll
        for (int j = 0; j < 8; ++j) {
            d[j] = g_decays[p + (size_t)j * DMODEL];
            v[j] = g_inj[p + (size_t)j * DMODEL];
        }
#pragma unroll
        for (int j = 0; j < 8; ++j) {
            s = fmaf(d[j], s, v[j]);
            A *= d[j];
        }
        p += (size_t)8 * DMODEL;
    }
    g_segA[g] = A;
    g_segB[g] = s;
}

__global__ __launch_bounds__(256)
void scan_pass2() {
    const int g = blockIdx.x * 256 + threadIdx.x;      // 0..8191
    const int e = g & (DMODEL - 1);
    const int b = g >> 10;
    float s = 0.0f;
#pragma unroll
    for (int seg = 0; seg < NSEG; ++seg) {
        int idx = ((b * NSEG + seg) << 10) | e;
        g_segInit[idx] = s;
        s = fmaf(g_segA[idx], s, g_segB[idx]);
    }
}

__global__ __launch_bounds__(256)
void scan_pass3(float* __restrict__ out) {
    const int g = blockIdx.x * 256 + threadIdx.x;
    const int e = g & (DMODEL - 1);
    const int bs = g >> 10;
    const int seg = bs & (NSEG - 1);
    const int b = bs >> 4;
    size_t p = ((size_t)b * SEQ + (size_t)seg * SEGLEN) * DMODEL + e;

    float s = g_segInit[g];
    for (int t = 0; t < SEGLEN; t += 8) {
        float d[8], v[8];
#pragma unroll
        for (int j = 0; j < 8; ++j) {
            d[j] = g_decays[p + (size_t)j * DMODEL];
            v[j] = g_inj[p + (size_t)j * DMODEL];
        }
#pragma unroll
        for (int j = 0; j < 8; ++j) {
            s = fmaf(d[j], s, v[j]);
            out[p + (size_t)j * DMODEL] = s;
        }
        p += (size_t)8 * DMODEL;
    }
}

// ---------------- launch ----------------
extern "C" void kernel_launch(void* const* d_in, const int* in_sizes, int n_in,
                              void* d_out, int out_size) {
    const float* x_seq   = (const float*)d_in[0];
    const float* W_decay = (const float*)d_in[1];
    const float* b_decay = (const float*)d_in[2];
    const float* W_input = (const float*)d_in[3];
    const float* b_input = (const float*)d_in[4];
    float* out = (float*)d_out;

    static bool attr_set = false;
    if (!attr_set) {
        cudaFuncSetAttribute(gemm_tc_kernel,
                             cudaFuncAttributeMaxDynamicSharedMemorySize, SMEM_TOTAL);
        attr_set = true;
    }

    // keep gemm_tc_kernel in the same ncu capture slot
    prof_align_kernel<<<1, 32>>>();

    convert_x_kernel<<<(MTOT * KTOT / 4) / 256, 256>>>(x_seq);
    convert_w_kernel<<<(NTOT * KTOT / 4) / 256, 256>>>(W_decay, W_input);

    dim3 grid(NTOT / N_TILE, MTOT / M_TILE);   // (16, 128): n fastest -> A reuse in L2
    gemm_tc_kernel<<<grid, GTHREADS, SMEM_TOTAL>>>(b_decay, b_input);

    scan_pass1<<<(BATCH * NSEG * DMODEL) / 256, 256>>>();
    scan_pass2<<<(BATCH * DMODEL) / 256, 256>>>();
    scan_pass3<<<(BATCH * NSEG * DMODEL) / 256, 256>>>(out);
}

// round 15
// speedup vs baseline: 1.1835x; 1.1835x over previous
#include <cuda_runtime.h>
#include <cuda_fp16.h>
#include <cstdint>

// ---------------- problem constants ----------------
#define BATCH   8
#define SEQ     4096
#define DMODEL  1024
#define MTOT    (BATCH * SEQ)      // 32768
#define KTOT    DMODEL             // 1024
#define NTOT    (2 * DMODEL)       // 2048 fused (decay | input)

// ---------------- GEMM tiling (R13 best config) ----------------
#define M_TILE   128
#define N_TILE   128
#define K_CHUNK  32
#define N_CHUNKS (KTOT / K_CHUNK)   // 32
#define GTHREADS 128
#define NSTAGE   5
#define LOOKAHEAD 3

// smem: padded pitch 40 fp16 (80 B) -> conflict-free ldmatrix
#define PITCH 40
#define A_TILE_BYTES (M_TILE * PITCH * 2)     // 10240
#define B_TILE_BYTES (N_TILE * PITCH * 2)     // 10240
#define OFF_A 0
#define OFF_B A_TILE_BYTES
#define STAGE_BYTES (A_TILE_BYTES + B_TILE_BYTES)  // 20480
#define SMEM_TOTAL  (NSTAGE * STAGE_BYTES)         // 102400 -> 2 CTAs/SM

// ---------------- scan segmentation ----------------
#define NSEG   16
#define SEGLEN (SEQ / NSEG)         // 256
#define HALF_D (DMODEL / 2)         // 512 half2 lanes

// ---------------- device scratch ----------------
__device__ __half X_hi[(size_t)MTOT * KTOT];
__device__ __half Wf_hi[(size_t)NTOT * KTOT];
__device__ __half g_decays[(size_t)MTOT * DMODEL];   // fp16 intermediates
__device__ __half g_inj[(size_t)MTOT * DMODEL];
__device__ float g_segA[BATCH * NSEG * DMODEL];
__device__ float g_segB[BATCH * NSEG * DMODEL];
__device__ float g_segInit[BATCH * NSEG * DMODEL];

// ---------------- PTX helpers ----------------
__device__ __forceinline__ uint32_t s2u(const void* p) {
    return (uint32_t)__cvta_generic_to_shared(p);
}

#define CPA16(s, g) asm volatile("cp.async.cg.shared.global [%0], [%1], 16;" :: "r"(s), "l"(g) : "memory")
#define CPA_COMMIT() asm volatile("cp.async.commit_group;" ::: "memory")
#define CPA_WAIT2()  asm volatile("cp.async.wait_group 2;" ::: "memory")
#define CPA_WAIT1()  asm volatile("cp.async.wait_group 1;" ::: "memory")
#define CPA_WAIT0()  asm volatile("cp.async.wait_group 0;" ::: "memory")

__device__ __forceinline__ void ldsm_x4(uint32_t addr, uint32_t& r0, uint32_t& r1,
                                        uint32_t& r2, uint32_t& r3) {
    asm volatile("ldmatrix.sync.aligned.m8n8.x4.shared.b16 {%0,%1,%2,%3}, [%4];"
                 : "=r"(r0), "=r"(r1), "=r"(r2), "=r"(r3) : "r"(addr));
}

// fp16 inputs, fp32 accumulate
__device__ __forceinline__ void mma_f32(float* c, const uint32_t* a,
                                        uint32_t b0, uint32_t b1) {
    asm volatile(
        "mma.sync.aligned.m16n8k16.row.col.f32.f16.f16.f32 "
        "{%0,%1,%2,%3}, {%4,%5,%6,%7}, {%8,%9}, {%0,%1,%2,%3};"
        : "+f"(c[0]), "+f"(c[1]), "+f"(c[2]), "+f"(c[3])
        : "r"(a[0]), "r"(a[1]), "r"(a[2]), "r"(a[3]), "r"(b0), "r"(b1));
}

// ---------------- ncu alignment no-op (keeps gemm in profiled launch slot) ----
__global__ void prof_align_kernel() {}

__global__ __launch_bounds__(256)
void convert_x_kernel(const float* __restrict__ x) {
    size_t i = (size_t)blockIdx.x * 256 + threadIdx.x;      // float4 index
    float4 v = reinterpret_cast<const float4*>(x)[i];
    __half2 uh0 = __halves2half2(__float2half_rn(v.x), __float2half_rn(v.y));
    __half2 uh1 = __halves2half2(__float2half_rn(v.z), __float2half_rn(v.w));
    reinterpret_cast<__half2*>(X_hi)[2 * i]     = uh0;
    reinterpret_cast<__half2*>(X_hi)[2 * i + 1] = uh1;
}

__global__ __launch_bounds__(256)
void convert_w_kernel(const float* __restrict__ Wd, const float* __restrict__ Wi) {
    size_t i = (size_t)blockIdx.x * 256 + threadIdx.x;      // float4 index, 524288
    int row = (int)(i >> 8);
    int c4  = (int)(i & 255);
    const float* src = (row < DMODEL) ? (Wd + (size_t)row * KTOT)
                                      : (Wi + (size_t)(row - DMODEL) * KTOT);
    float4 v = reinterpret_cast<const float4*>(src)[c4];
    __half2 uh0 = __halves2half2(__float2half_rn(v.x), __float2half_rn(v.y));
    __half2 uh1 = __halves2half2(__float2half_rn(v.z), __float2half_rn(v.w));
    reinterpret_cast<__half2*>(Wf_hi)[2 * i]     = uh0;
    reinterpret_cast<__half2*>(Wf_hi)[2 * i + 1] = uh1;
}

// ---------------- GEMM: load one K-chunk into a stage ----------------
// 128 threads: A = 128 rows x 4 16B-chunks = 512 transfers (4 iters); B same.
__device__ __forceinline__ void load_chunk(uint32_t smem_u, int c, int st,
                                           int m0, int n0, int tid) {
    const int k0 = c * K_CHUNK;
    const uint32_t base = smem_u + st * STAGE_BYTES;
#pragma unroll
    for (int it = 0; it < 4; ++it) {
        int idx = it * 128 + tid;
        int row = idx >> 2;
        int kk  = (idx & 3) * 8;
        uint32_t so = (uint32_t)(row * PITCH + kk) * 2;
        size_t gA = (size_t)(m0 + row) * KTOT + k0 + kk;
        size_t gB = (size_t)(n0 + row) * KTOT + k0 + kk;
        CPA16(base + OFF_A + so, X_hi + gA);
        CPA16(base + OFF_B + so, Wf_hi + gB);
    }
}

// ---------------- GEMM + gate epilogue (single-pass fp16, fp32 accum) ---------
// 4 warps: 2(m) x 2(n); warp tile 64x64; fragment double-buffer pipelined
// across the chunk barrier; 2 CTAs/SM; fp16 half2 epilogue stores.
__global__ __launch_bounds__(GTHREADS, 2)
void gemm_tc_kernel(const float* __restrict__ bd, const float* __restrict__ bi) {
    extern __shared__ char smem[];
    const uint32_t smem_u = s2u(smem);
    const int tid = threadIdx.x;
    const int wid = tid >> 5;
    const int lane = tid & 31;

    const int n0 = blockIdx.x * N_TILE;        // 0..1920
    const int m0 = blockIdx.y * M_TILE;
    const bool is_decay = (n0 < DMODEL);
    const int colbase = is_decay ? n0 : (n0 - DMODEL);
    const float* bv = is_decay ? bd : bi;

    const int warp_m = (wid & 1) * 64;         // 2 warps along M (64 rows)
    const int warp_n = (wid >> 1) * 64;        // 2 warps along N (64 cols)

    float acc[4][8][4];
#pragma unroll
    for (int mt = 0; mt < 4; ++mt)
#pragma unroll
        for (int nt = 0; nt < 8; ++nt)
#pragma unroll
            for (int q = 0; q < 4; ++q) acc[mt][nt][q] = 0.0f;

    // ldmatrix lane addressing
    const int a_r = lane & 15;
    const int a_c = (lane >> 4) * 8;
    const int b_quad = lane >> 3;
    const int b_r = lane & 7;
    const int b_row_off = ((b_quad >> 1) * 8) + b_r;
    const int b_k_off = (b_quad & 1) * 8;

    uint32_t ah[2][4][4];                      // [buf][mt][reg]
    uint32_t bh[2][4][4];                      // [buf][ng][reg]

#define LOAD_FRAGS(buf, base, kc)                                              \
    do {                                                                       \
        _Pragma("unroll")                                                      \
        for (int mt = 0; mt < 4; ++mt) {                                       \
            uint32_t off = (uint32_t)((warp_m + mt * 16 + a_r) * PITCH + (kc) + a_c) * 2; \
            ldsm_x4((base) + OFF_A + off, ah[buf][mt][0], ah[buf][mt][1],      \
                    ah[buf][mt][2], ah[buf][mt][3]);                           \
        }                                                                      \
        _Pragma("unroll")                                                      \
        for (int ng = 0; ng < 4; ++ng) {                                       \
            uint32_t off = (uint32_t)((warp_n + ng * 16 + b_row_off) * PITCH + (kc) + b_k_off) * 2; \
            ldsm_x4((base) + OFF_B + off, bh[buf][ng][0], bh[buf][ng][1],      \
                    bh[buf][ng][2], bh[buf][ng][3]);                           \
        }                                                                      \
    } while (0)

#define MMA_FRAGS(buf)                                                         \
    do {                                                                       \
        _Pragma("unroll")                                                      \
        for (int ng = 0; ng < 4; ++ng)                                         \
            _Pragma("unroll")                                                  \
            for (int mt = 0; mt < 4; ++mt) {                                   \
                mma_f32(acc[mt][2 * ng + 0], ah[buf][mt], bh[buf][ng][0], bh[buf][ng][1]); \
                mma_f32(acc[mt][2 * ng + 1], ah[buf][mt], bh[buf][ng][2], bh[buf][ng][3]); \
            }                                                                  \
    } while (0)

    // prologue: LOOKAHEAD chunk-loads in flight, then preload chunk0 kh0 frags
#pragma unroll
    for (int c = 0; c < LOOKAHEAD; ++c) {
        load_chunk(smem_u, c, c, m0, n0, tid);
        CPA_COMMIT();
    }
    CPA_WAIT2();                               // chunk 0 data complete
    __syncthreads();
    LOAD_FRAGS(0, smem_u + 0 * STAGE_BYTES, 0);

    int st = 0;                                // = c % NSTAGE
    int lst = LOOKAHEAD;                       // = (c+LOOKAHEAD) % NSTAGE
    for (int c = 0; c < N_CHUNKS; ++c) {
        if (c + LOOKAHEAD < N_CHUNKS) {
            load_chunk(smem_u, c + LOOKAHEAD, lst, m0, n0, tid);
            CPA_COMMIT();
        }
        // ensure data of chunk c AND c+1 are resident (cross-chunk prefetch)
        {
            int hi = (c + LOOKAHEAD < N_CHUNKS) ? (c + LOOKAHEAD) : (N_CHUNKS - 1);
            int lo = (c + 1 < N_CHUNKS) ? (c + 1) : (N_CHUNKS - 1);
            int rem = hi - lo;                 // 2,...,2,1,0,0
            if      (rem >= 2) { CPA_WAIT2(); }
            else if (rem == 1) { CPA_WAIT1(); }
            else               { CPA_WAIT0(); }
        }
        __syncthreads();

        const uint32_t base = smem_u + st * STAGE_BYTES;
        int nst = st + 1; if (nst == NSTAGE) nst = 0;
        const uint32_t nbase = smem_u + nst * STAGE_BYTES;

        // phase kh0: fetch kh1 frags while doing kh0 MMAs
        LOAD_FRAGS(1, base, 16);
        MMA_FRAGS(0);
        // phase kh1: fetch next chunk's kh0 frags while doing kh1 MMAs
        if (c + 1 < N_CHUNKS) {
            LOAD_FRAGS(0, nbase, 0);
        }
        MMA_FRAGS(1);

        ++st;  if (st  == NSTAGE) st  = 0;
        ++lst; if (lst == NSTAGE) lst = 0;
    }

    // ---- epilogue: bias (+sigmoid), fp16 half2 stores ----
    __half* dst = is_decay ? g_decays : g_inj;
#pragma unroll
    for (int mt = 0; mt < 4; ++mt) {
        int row0 = m0 + warp_m + mt * 16 + (lane >> 2);
#pragma unroll
        for (int nt = 0; nt < 8; ++nt) {
            int gcol = colbase + warp_n + nt * 8 + (lane & 3) * 2;
            float2 bias2 = *reinterpret_cast<const float2*>(bv + gcol);
            float v0 = acc[mt][nt][0] + bias2.x;
            float v1 = acc[mt][nt][1] + bias2.y;
            float v2 = acc[mt][nt][2] + bias2.x;
            float v3 = acc[mt][nt][3] + bias2.y;
            if (is_decay) {
                v0 = __fdividef(1.0f, 1.0f + __expf(-v0));
                v1 = __fdividef(1.0f, 1.0f + __expf(-v1));
                v2 = __fdividef(1.0f, 1.0f + __expf(-v2));
                v3 = __fdividef(1.0f, 1.0f + __expf(-v3));
            }
            *reinterpret_cast<__half2*>(dst + (size_t)row0 * DMODEL + gcol) =
                __floats2half2_rn(v0, v1);
            *reinterpret_cast<__half2*>(dst + (size_t)(row0 + 8) * DMODEL + gcol) =
                __floats2half2_rn(v2, v3);
        }
    }
#undef LOAD_FRAGS
#undef MMA_FRAGS
}

// ---------------- segmented scan (fp16 in, 2 channels per thread) -------------
__global__ __launch_bounds__(256)
void scan_pass1() {
    const int g = blockIdx.x * 256 + threadIdx.x;      // 0..65535
    const int ep = g & (HALF_D - 1);                   // half2 lane (2 channels)
    const int bs = g >> 9;                             // b*NSEG + seg
    const int seg = bs & (NSEG - 1);
    const int b = bs >> 4;
    size_t p = ((size_t)b * SEQ + (size_t)seg * SEGLEN) * HALF_D + ep;
    const __half2* dh = reinterpret_cast<const __half2*>(g_decays);
    const __half2* vh = reinterpret_cast<const __half2*>(g_inj);

    float s0 = 0.0f, s1 = 0.0f, A0 = 1.0f, A1 = 1.0f;
    for (int t = 0; t < SEGLEN; t += 8) {
        float2 d[8], v[8];
#pragma unroll
        for (int j = 0; j < 8; ++j) {
            d[j] = __half22float2(dh[p + (size_t)j * HALF_D]);
            v[j] = __half22float2(vh[p + (size_t)j * HALF_D]);
        }
#pragma unroll
        for (int j = 0; j < 8; ++j) {
            s0 = fmaf(d[j].x, s0, v[j].x);  A0 *= d[j].x;
            s1 = fmaf(d[j].y, s1, v[j].y);  A1 *= d[j].y;
        }
        p += (size_t)8 * HALF_D;
    }
    const int idx = (bs << 10) | (ep * 2);
    g_segA[idx]     = A0;  g_segA[idx + 1] = A1;
    g_segB[idx]     = s0;  g_segB[idx + 1] = s1;
}

__global__ __launch_bounds__(256)
void scan_pass2() {
    const int g = blockIdx.x * 256 + threadIdx.x;      // 0..8191
    const int e = g & (DMODEL - 1);
    const int b = g >> 10;
    float s = 0.0f;
#pragma unroll
    for (int seg = 0; seg < NSEG; ++seg) {
        int idx = ((b * NSEG + seg) << 10) | e;
        g_segInit[idx] = s;
        s = fmaf(g_segA[idx], s, g_segB[idx]);
    }
}

__global__ __launch_bounds__(256)
void scan_pass3(float* __restrict__ out) {
    const int g = blockIdx.x * 256 + threadIdx.x;      // 0..65535
    const int ep = g & (HALF_D - 1);
    const int bs = g >> 9;
    const int seg = bs & (NSEG - 1);
    const int b = bs >> 4;
    size_t p = ((size_t)b * SEQ + (size_t)seg * SEGLEN) * HALF_D + ep;
    const __half2* dh = reinterpret_cast<const __half2*>(g_decays);
    const __half2* vh = reinterpret_cast<const __half2*>(g_inj);
    const int idx = (bs << 10) | (ep * 2);
    float s0 = g_segInit[idx];
    float s1 = g_segInit[idx + 1];
    size_t q = ((size_t)b * SEQ + (size_t)seg * SEGLEN) * DMODEL + ep * 2;

    for (int t = 0; t < SEGLEN; t += 8) {
        float2 d[8], v[8];
#pragma unroll
        for (int j = 0; j < 8; ++j) {
            d[j] = __half22float2(dh[p + (size_t)j * HALF_D]);
            v[j] = __half22float2(vh[p + (size_t)j * HALF_D]);
        }
#pragma unroll
        for (int j = 0; j < 8; ++j) {
            s0 = fmaf(d[j].x, s0, v[j].x);
            s1 = fmaf(d[j].y, s1, v[j].y);
            *reinterpret_cast<float2*>(out + q + (size_t)j * DMODEL) =
                make_float2(s0, s1);
        }
        p += (size_t)8 * HALF_D;
        q += (size_t)8 * DMODEL;
    }
}

// ---------------- launch ----------------
extern "C" void kernel_launch(void* const* d_in, const int* in_sizes, int n_in,
                              void* d_out, int out_size) {
    const float* x_seq   = (const float*)d_in[0];
    const float* W_decay = (const float*)d_in[1];
    const float* b_decay = (const float*)d_in[2];
    const float* W_input = (const float*)d_in[3];
    const float* b_input = (const float*)d_in[4];
    float* out = (float*)d_out;

    static bool attr_set = false;
    if (!attr_set) {
        cudaFuncSetAttribute(gemm_tc_kernel,
                             cudaFuncAttributeMaxDynamicSharedMemorySize, SMEM_TOTAL);
        attr_set = true;
    }

    // keep gemm_tc_kernel in the same ncu capture slot
    prof_align_kernel<<<1, 32>>>();

    convert_x_kernel<<<(MTOT * KTOT / 4) / 256, 256>>>(x_seq);
    convert_w_kernel<<<(NTOT * KTOT / 4) / 256, 256>>>(W_decay, W_input);

    dim3 grid(NTOT / N_TILE, MTOT / M_TILE);   // (16, 256): n fastest -> A reuse in L2
    gemm_tc_kernel<<<grid, GTHREADS, SMEM_TOTAL>>>(b_decay, b_input);

    scan_pass1<<<(BATCH * NSEG * HALF_D) / 256, 256>>>();
    scan_pass2<<<(BATCH * DMODEL) / 256, 256>>>();
    scan_pass3<<<(BATCH * NSEG * HALF_D) / 256, 256>>>(out);
}

// round 16
// speedup vs baseline: 1.3691x; 1.1569x over previous
#include <cuda_runtime.h>
#include <cuda.h>
#include <cuda_fp16.h>
#include <cstdint>

// ---------------- problem constants ----------------
#define BATCH   8
#define SEQ     4096
#define DMODEL  1024
#define MTOT    (BATCH * SEQ)      // 32768
#define KTOT    DMODEL             // 1024
#define NTOT    (2 * DMODEL)       // 2048 fused (decay | input)

// ---------------- GEMM tiling ----------------
#define M_TILE   128
#define N_TILE   128
#define K_CHUNK  64
#define N_CHUNKS (KTOT / K_CHUNK)   // 16
#define GTHREADS 128
#define NSTAGE   3

// smem: TMA SW128 tiles, 128 B per row (64 fp16)
#define ROW_BYTES 128
#define A_TILE_BYTES (M_TILE * ROW_BYTES)     // 16384
#define B_TILE_BYTES (N_TILE * ROW_BYTES)     // 16384
#define OFF_A 0
#define OFF_B A_TILE_BYTES
#define STAGE_BYTES (A_TILE_BYTES + B_TILE_BYTES)  // 32768
#define MBAR_OFF (NSTAGE * STAGE_BYTES)            // 98304
#define SMEM_TOTAL  (MBAR_OFF + 64)                // 98368 -> 2 CTAs/SM

// ---------------- scan segmentation ----------------
#define NSEG   16
#define SEGLEN (SEQ / NSEG)         // 256
#define HALF_D (DMODEL / 2)         // 512 half2 lanes

// ---------------- device scratch ----------------
__device__ __half X_hi[(size_t)MTOT * KTOT];
__device__ __half Wf_hi[(size_t)NTOT * KTOT];
__device__ __half g_decays[(size_t)MTOT * DMODEL];   // fp16 intermediates
__device__ __half g_inj[(size_t)MTOT * DMODEL];
__device__ float g_segA[BATCH * NSEG * DMODEL];
__device__ float g_segB[BATCH * NSEG * DMODEL];
__device__ float g_segInit[BATCH * NSEG * DMODEL];

// ---------------- PTX helpers ----------------
__device__ __forceinline__ uint32_t s2u(const void* p) {
    return (uint32_t)__cvta_generic_to_shared(p);
}
__device__ __forceinline__ uint32_t sw128(uint32_t off) {
    return off ^ ((off >> 3) & 0x70);
}

#define MBARRIER_INIT(a, n) asm volatile("mbarrier.init.shared.b64 [%0], %1;" :: "r"(a), "r"(n) : "memory")
#define MBARRIER_EXPECT_TX(a, b) asm volatile("mbarrier.arrive.expect_tx.shared.b64 _, [%0], %1;" :: "r"(a), "r"(b) : "memory")
#define FENCE_PROXY_ASYNC() asm volatile("fence.proxy.async.shared::cta;" ::: "memory")

#define MBARRIER_WAIT_PARITY(mbar, parity) do {                               \
    uint32_t _m = (mbar); uint32_t _p = (parity); uint32_t _done;             \
    asm volatile("{\n\t.reg .pred p;\n\t"                                     \
        "mbarrier.try_wait.parity.acquire.cta.shared::cta.b64 p, [%1], %2;\n\t" \
        "selp.b32 %0, 1, 0, p;\n\t}"                                          \
        : "=r"(_done) : "r"(_m), "r"(_p) : "memory");                         \
    if (!_done) {                                                             \
        asm volatile("{\n\t.reg .pred P1;\n\t"                                \
            "WL_%=:\n\t"                                                      \
            "mbarrier.try_wait.parity.acquire.cta.shared::cta.b64 P1, [%0], %1, 0x989680;\n\t" \
            "@P1 bra.uni WD_%=;\n\t"                                          \
            "bra.uni WL_%=;\n\t"                                              \
            "WD_%=:\n\t}" :: "r"(_m), "r"(_p) : "memory");                    \
    }                                                                         \
} while (0)

__device__ __forceinline__ void tma_load_2d(uint32_t smem_addr, const CUtensorMap* tmap,
                                            int cx, int cy, uint32_t mbar) {
    asm volatile(
        "cp.async.bulk.tensor.2d.shared::cta.global.tile.mbarrier::complete_tx::bytes "
        "[%0], [%1, {%2, %3}], [%4];"
        :: "r"(smem_addr), "l"(tmap), "r"(cx), "r"(cy), "r"(mbar) : "memory");
}

__device__ __forceinline__ void ldsm_x4(uint32_t addr, uint32_t& r0, uint32_t& r1,
                                        uint32_t& r2, uint32_t& r3) {
    asm volatile("ldmatrix.sync.aligned.m8n8.x4.shared.b16 {%0,%1,%2,%3}, [%4];"
                 : "=r"(r0), "=r"(r1), "=r"(r2), "=r"(r3) : "r"(addr));
}

// fp16 inputs, fp32 accumulate
__device__ __forceinline__ void mma_f32(float* c, const uint32_t* a,
                                        uint32_t b0, uint32_t b1) {
    asm volatile(
        "mma.sync.aligned.m16n8k16.row.col.f32.f16.f16.f32 "
        "{%0,%1,%2,%3}, {%4,%5,%6,%7}, {%8,%9}, {%0,%1,%2,%3};"
        : "+f"(c[0]), "+f"(c[1]), "+f"(c[2]), "+f"(c[3])
        : "r"(a[0]), "r"(a[1]), "r"(a[2]), "r"(a[3]), "r"(b0), "r"(b1));
}

// ---------------- ncu alignment no-op (keeps gemm in profiled launch slot) ----
__global__ void prof_align_kernel() {}

__global__ __launch_bounds__(256)
void convert_x_kernel(const float* __restrict__ x) {
    size_t i = (size_t)blockIdx.x * 256 + threadIdx.x;      // float4 index
    float4 v = reinterpret_cast<const float4*>(x)[i];
    __half2 uh0 = __halves2half2(__float2half_rn(v.x), __float2half_rn(v.y));
    __half2 uh1 = __halves2half2(__float2half_rn(v.z), __float2half_rn(v.w));
    reinterpret_cast<__half2*>(X_hi)[2 * i]     = uh0;
    reinterpret_cast<__half2*>(X_hi)[2 * i + 1] = uh1;
}

__global__ __launch_bounds__(256)
void convert_w_kernel(const float* __restrict__ Wd, const float* __restrict__ Wi) {
    size_t i = (size_t)blockIdx.x * 256 + threadIdx.x;      // float4 index, 524288
    int row = (int)(i >> 8);
    int c4  = (int)(i & 255);
    const float* src = (row < DMODEL) ? (Wd + (size_t)row * KTOT)
                                      : (Wi + (size_t)(row - DMODEL) * KTOT);
    float4 v = reinterpret_cast<const float4*>(src)[c4];
    __half2 uh0 = __halves2half2(__float2half_rn(v.x), __float2half_rn(v.y));
    __half2 uh1 = __halves2half2(__float2half_rn(v.z), __float2half_rn(v.w));
    reinterpret_cast<__half2*>(Wf_hi)[2 * i]     = uh0;
    reinterpret_cast<__half2*>(Wf_hi)[2 * i + 1] = uh1;
}

// ---------------- GEMM + gate epilogue (TMA loads, single-pass fp16) ----------
// 4 warps: 2(m) x 2(n); warp tile 64x64; K64 chunks, 4 kh-phases with fragment
// double-buffer; TMA per-stage mbarrier pipeline (NSTAGE=3, depth 2); 2 CTAs/SM.
__global__ __launch_bounds__(GTHREADS, 2)
void gemm_tc_kernel(const __grid_constant__ CUtensorMap tmA,
                    const __grid_constant__ CUtensorMap tmB,
                    const float* __restrict__ bd, const float* __restrict__ bi) {
    extern __shared__ char smem[];
    const uint32_t smem_u = s2u(smem);
    const int tid = threadIdx.x;
    const int wid = tid >> 5;
    const int lane = tid & 31;

    const int n0 = blockIdx.x * N_TILE;        // 0..1920
    const int m0 = blockIdx.y * M_TILE;
    const bool is_decay = (n0 < DMODEL);
    const int colbase = is_decay ? n0 : (n0 - DMODEL);
    const float* bv = is_decay ? bd : bi;

    const int warp_m = (wid & 1) * 64;         // 2 warps along M (64 rows)
    const int warp_n = (wid >> 1) * 64;        // 2 warps along N (64 cols)

    float acc[4][8][4];
#pragma unroll
    for (int mt = 0; mt < 4; ++mt)
#pragma unroll
        for (int nt = 0; nt < 8; ++nt)
#pragma unroll
            for (int q = 0; q < 4; ++q) acc[mt][nt][q] = 0.0f;

    // ldmatrix lane addressing (byte columns within 128B SW128 rows)
    const int a_r = lane & 15;
    const int a_cb = (lane >> 4) * 16;         // 0 or 16 bytes
    const int b_quad = lane >> 3;
    const int b_r = lane & 7;
    const int b_row_off = ((b_quad >> 1) * 8) + b_r;
    const int b_kb = (b_quad & 1) * 16;        // 0 or 16 bytes

    uint32_t ah[2][4][4];                      // [buf][mt][reg]
    uint32_t bh[2][4][4];                      // [buf][ng][reg]

    // kcb = byte column of the k16 slice within the 128B row (0,32,64,96)
#define LOAD_FRAGS(buf, base, kcb)                                             \
    do {                                                                       \
        _Pragma("unroll")                                                      \
        for (int mt = 0; mt < 4; ++mt) {                                       \
            uint32_t bo = (uint32_t)((warp_m + mt * 16 + a_r) * ROW_BYTES + (kcb) + a_cb); \
            ldsm_x4((base) + OFF_A + sw128(bo), ah[buf][mt][0], ah[buf][mt][1],\
                    ah[buf][mt][2], ah[buf][mt][3]);                           \
        }                                                                      \
        _Pragma("unroll")                                                      \
        for (int ng = 0; ng < 4; ++ng) {                                       \
            uint32_t bo = (uint32_t)((warp_n + ng * 16 + b_row_off) * ROW_BYTES + (kcb) + b_kb); \
            ldsm_x4((base) + OFF_B + sw128(bo), bh[buf][ng][0], bh[buf][ng][1],\
                    bh[buf][ng][2], bh[buf][ng][3]);                           \
        }                                                                      \
    } while (0)

#define MMA_FRAGS(buf)                                                         \
    do {                                                                       \
        _Pragma("unroll")                                                      \
        for (int ng = 0; ng < 4; ++ng)                                         \
            _Pragma("unroll")                                                  \
            for (int mt = 0; mt < 4; ++mt) {                                   \
                mma_f32(acc[mt][2 * ng + 0], ah[buf][mt], bh[buf][ng][0], bh[buf][ng][1]); \
                mma_f32(acc[mt][2 * ng + 1], ah[buf][mt], bh[buf][ng][2], bh[buf][ng][3]); \
            }                                                                  \
    } while (0)

    // ---- mbarrier + TMA prologue ----
    const uint32_t mbar0 = smem_u + MBAR_OFF;
    if (tid == 0) {
        MBARRIER_INIT(mbar0 + 0, 1);
        MBARRIER_INIT(mbar0 + 8, 1);
        MBARRIER_INIT(mbar0 + 16, 1);
        FENCE_PROXY_ASYNC();
    }
    __syncthreads();
    if (tid == 0) {
#pragma unroll
        for (int c = 0; c < 2; ++c) {
            const uint32_t sb = smem_u + c * STAGE_BYTES;
            MBARRIER_EXPECT_TX(mbar0 + c * 8, STAGE_BYTES);
            tma_load_2d(sb + OFF_A, &tmA, c * K_CHUNK, m0, mbar0 + c * 8);
            tma_load_2d(sb + OFF_B, &tmB, c * K_CHUNK, n0, mbar0 + c * 8);
        }
    }

    int ph0 = 0, ph1 = 0, ph2 = 0;
    int st = 0;
    for (int c = 0; c < N_CHUNKS; ++c) {
        __syncthreads();                       // all warps done with chunk c-1
        if (tid == 0 && c + 2 < N_CHUNKS) {    // refill stage (c+2)%3
            int wst = st + 2; if (wst >= NSTAGE) wst -= NSTAGE;
            const uint32_t sb = smem_u + wst * STAGE_BYTES;
            MBARRIER_EXPECT_TX(mbar0 + wst * 8, STAGE_BYTES);
            tma_load_2d(sb + OFF_A, &tmA, (c + 2) * K_CHUNK, m0, mbar0 + wst * 8);
            tma_load_2d(sb + OFF_B, &tmB, (c + 2) * K_CHUNK, n0, mbar0 + wst * 8);
        }
        // wait chunk c data
        if (st == 0)      { MBARRIER_WAIT_PARITY(mbar0 + 0,  ph0); ph0 ^= 1; }
        else if (st == 1) { MBARRIER_WAIT_PARITY(mbar0 + 8,  ph1); ph1 ^= 1; }
        else              { MBARRIER_WAIT_PARITY(mbar0 + 16, ph2); ph2 ^= 1; }

        const uint32_t base = smem_u + st * STAGE_BYTES;
        // 4 kh-phases: L0; L1|M0; L2|M1; L3|M2; M3
        LOAD_FRAGS(0, base, 0);
        LOAD_FRAGS(1, base, 32);
        MMA_FRAGS(0);
        LOAD_FRAGS(0, base, 64);
        MMA_FRAGS(1);
        LOAD_FRAGS(1, base, 96);
        MMA_FRAGS(0);
        MMA_FRAGS(1);

        ++st; if (st == NSTAGE) st = 0;
    }

    // ---- epilogue: bias (+sigmoid), fp16 half2 stores ----
    __half* dst = is_decay ? g_decays : g_inj;
#pragma unroll
    for (int mt = 0; mt < 4; ++mt) {
        int row0 = m0 + warp_m + mt * 16 + (lane >> 2);
#pragma unroll
        for (int nt = 0; nt < 8; ++nt) {
            int gcol = colbase + warp_n + nt * 8 + (lane & 3) * 2;
            float2 bias2 = *reinterpret_cast<const float2*>(bv + gcol);
            float v0 = acc[mt][nt][0] + bias2.x;
            float v1 = acc[mt][nt][1] + bias2.y;
            float v2 = acc[mt][nt][2] + bias2.x;
            float v3 = acc[mt][nt][3] + bias2.y;
            if (is_decay) {
                v0 = __fdividef(1.0f, 1.0f + __expf(-v0));
                v1 = __fdividef(1.0f, 1.0f + __expf(-v1));
                v2 = __fdividef(1.0f, 1.0f + __expf(-v2));
                v3 = __fdividef(1.0f, 1.0f + __expf(-v3));
            }
            *reinterpret_cast<__half2*>(dst + (size_t)row0 * DMODEL + gcol) =
                __floats2half2_rn(v0, v1);
            *reinterpret_cast<__half2*>(dst + (size_t)(row0 + 8) * DMODEL + gcol) =
                __floats2half2_rn(v2, v3);
        }
    }
#undef LOAD_FRAGS
#undef MMA_FRAGS
}

// ---------------- segmented scan (fp16 in, 2 channels per thread) -------------
__global__ __launch_bounds__(256)
void scan_pass1() {
    const int g = blockIdx.x * 256 + threadIdx.x;      // 0..65535
    const int ep = g & (HALF_D - 1);                   // half2 lane (2 channels)
    const int bs = g >> 9;                             // b*NSEG + seg
    const int seg = bs & (NSEG - 1);
    const int b = bs >> 4;
    size_t p = ((size_t)b * SEQ + (size_t)seg * SEGLEN) * HALF_D + ep;
    const __half2* dh = reinterpret_cast<const __half2*>(g_decays);
    const __half2* vh = reinterpret_cast<const __half2*>(g_inj);

    float s0 = 0.0f, s1 = 0.0f, A0 = 1.0f, A1 = 1.0f;
    for (int t = 0; t < SEGLEN; t += 8) {
        float2 d[8], v[8];
#pragma unroll
        for (int j = 0; j < 8; ++j) {
            d[j] = __half22float2(dh[p + (size_t)j * HALF_D]);
            v[j] = __half22float2(vh[p + (size_t)j * HALF_D]);
        }
#pragma unroll
        for (int j = 0; j < 8; ++j) {
            s0 = fmaf(d[j].x, s0, v[j].x);  A0 *= d[j].x;
            s1 = fmaf(d[j].y, s1, v[j].y);  A1 *= d[j].y;
        }
        p += (size_t)8 * HALF_D;
    }
    const int idx = (bs << 10) | (ep * 2);
    g_segA[idx]     = A0;  g_segA[idx + 1] = A1;
    g_segB[idx]     = s0;  g_segB[idx + 1] = s1;
}

__global__ __launch_bounds__(256)
void scan_pass2() {
    const int g = blockIdx.x * 256 + threadIdx.x;      // 0..8191
    const int e = g & (DMODEL - 1);
    const int b = g >> 10;
    float s = 0.0f;
#pragma unroll
    for (int seg = 0; seg < NSEG; ++seg) {
        int idx = ((b * NSEG + seg) << 10) | e;
        g_segInit[idx] = s;
        s = fmaf(g_segA[idx], s, g_segB[idx]);
    }
}

__global__ __launch_bounds__(256)
void scan_pass3(float* __restrict__ out) {
    const int g = blockIdx.x * 256 + threadIdx.x;      // 0..65535
    const int ep = g & (HALF_D - 1);
    const int bs = g >> 9;
    const int seg = bs & (NSEG - 1);
    const int b = bs >> 4;
    size_t p = ((size_t)b * SEQ + (size_t)seg * SEGLEN) * HALF_D + ep;
    const __half2* dh = reinterpret_cast<const __half2*>(g_decays);
    const __half2* vh = reinterpret_cast<const __half2*>(g_inj);
    const int idx = (bs << 10) | (ep * 2);
    float s0 = g_segInit[idx];
    float s1 = g_segInit[idx + 1];
    size_t q = ((size_t)b * SEQ + (size_t)seg * SEGLEN) * DMODEL + ep * 2;

    for (int t = 0; t < SEGLEN; t += 8) {
        float2 d[8], v[8];
#pragma unroll
        for (int j = 0; j < 8; ++j) {
            d[j] = __half22float2(dh[p + (size_t)j * HALF_D]);
            v[j] = __half22float2(vh[p + (size_t)j * HALF_D]);
        }
#pragma unroll
        for (int j = 0; j < 8; ++j) {
            s0 = fmaf(d[j].x, s0, v[j].x);
            s1 = fmaf(d[j].y, s1, v[j].y);
            *reinterpret_cast<float2*>(out + q + (size_t)j * DMODEL) =
                make_float2(s0, s1);
        }
        p += (size_t)8 * HALF_D;
        q += (size_t)8 * DMODEL;
    }
}

// ---------------- host: tensormap construction ----------------
typedef CUresult (*PFN_cuTensorMapEncodeTiled_t)(
    CUtensorMap*, CUtensorMapDataType, cuuint32_t, void*,
    const cuuint64_t*, const cuuint64_t*, const cuuint32_t*, const cuuint32_t*,
    CUtensorMapInterleave, CUtensorMapSwizzle, CUtensorMapL2promotion,
    CUtensorMapFloatOOBfill);

static void build_tmap(PFN_cuTensorMapEncodeTiled_t enc, CUtensorMap* tm,
                       void* ptr, uint64_t rows) {
    cuuint64_t dims[2]    = {(cuuint64_t)KTOT, (cuuint64_t)rows};
    cuuint64_t strides[1] = {(cuuint64_t)KTOT * 2};
    cuuint32_t box[2]     = {K_CHUNK, 128};
    cuuint32_t estr[2]    = {1, 1};
    enc(tm, CU_TENSOR_MAP_DATA_TYPE_FLOAT16, 2, ptr, dims, strides, box, estr,
        CU_TENSOR_MAP_INTERLEAVE_NONE, CU_TENSOR_MAP_SWIZZLE_128B,
        CU_TENSOR_MAP_L2_PROMOTION_L2_128B, CU_TENSOR_MAP_FLOAT_OOB_FILL_NONE);
}

// ---------------- launch ----------------
extern "C" void kernel_launch(void* const* d_in, const int* in_sizes, int n_in,
                              void* d_out, int out_size) {
    const float* x_seq   = (const float*)d_in[0];
    const float* W_decay = (const float*)d_in[1];
    const float* b_decay = (const float*)d_in[2];
    const float* W_input = (const float*)d_in[3];
    const float* b_input = (const float*)d_in[4];
    float* out = (float*)d_out;

    static bool init_done = false;
    static CUtensorMap tmA, tmB;
    if (!init_done) {
        cudaFuncSetAttribute(gemm_tc_kernel,
                             cudaFuncAttributeMaxDynamicSharedMemorySize, SMEM_TOTAL);
        PFN_cuTensorMapEncodeTiled_t enc = nullptr;
        cudaDriverEntryPointQueryResult qres;
        cudaGetDriverEntryPoint("cuTensorMapEncodeTiled", (void**)&enc,
                                cudaEnableDefault, &qres);
        void *pX = nullptr, *pW = nullptr;
        cudaGetSymbolAddress(&pX, X_hi);
        cudaGetSymbolAddress(&pW, Wf_hi);
        build_tmap(enc, &tmA, pX, MTOT);
        build_tmap(enc, &tmB, pW, NTOT);
        init_done = true;
    }

    // keep gemm_tc_kernel in the same ncu capture slot
    prof_align_kernel<<<1, 32>>>();

    convert_x_kernel<<<(MTOT * KTOT / 4) / 256, 256>>>(x_seq);
    convert_w_kernel<<<(NTOT * KTOT / 4) / 256, 256>>>(W_decay, W_input);

    dim3 grid(NTOT / N_TILE, MTOT / M_TILE);   // (16, 256): n fastest -> A reuse in L2
    gemm_tc_kernel<<<grid, GTHREADS, SMEM_TOTAL>>>(tmA, tmB, b_decay, b_input);

    scan_pass1<<<(BATCH * NSEG * HALF_D) / 256, 256>>>();
    scan_pass2<<<(BATCH * DMODEL) / 256, 256>>>();
    scan_pass3<<<(BATCH * NSEG * HALF_D) / 256, 256>>>(out);
}

// round 17
// speedup vs baseline: 1.3779x; 1.0064x over previous
#include <cuda_runtime.h>
#include <cuda.h>
#include <cuda_fp16.h>
#include <cstdint>

// ---------------- problem constants ----------------
#define BATCH   8
#define SEQ     4096
#define DMODEL  1024
#define MTOT    (BATCH * SEQ)      // 32768
#define KTOT    DMODEL             // 1024
#define NTOT    (2 * DMODEL)       // 2048 fused (decay | input)

// ---------------- GEMM tiling ----------------
#define M_TILE   128
#define N_TILE   128
#define K_CHUNK  64
#define N_CHUNKS (KTOT / K_CHUNK)   // 16
#define GTHREADS 128
#define NSTAGE   3

// smem: TMA SW128 tiles, 128 B per row (64 fp16)
#define ROW_BYTES 128
#define A_TILE_BYTES (M_TILE * ROW_BYTES)     // 16384
#define B_TILE_BYTES (N_TILE * ROW_BYTES)     // 16384
#define OFF_A 0
#define OFF_B A_TILE_BYTES
#define STAGE_BYTES (A_TILE_BYTES + B_TILE_BYTES)  // 32768
#define MBAR_OFF (NSTAGE * STAGE_BYTES)            // 98304
#define SMEM_TOTAL  (MBAR_OFF + 64)                // 98368 -> 2 CTAs/SM

// ---------------- scan segmentation ----------------
#define NSEG   16
#define SEGLEN (SEQ / NSEG)         // 256
#define HALF_D (DMODEL / 2)         // 512 half2 lanes

// ---------------- device scratch ----------------
__device__ __half X_hi[(size_t)MTOT * KTOT];
__device__ __half Wf_hi[(size_t)NTOT * KTOT];
__device__ __half g_decays[(size_t)MTOT * DMODEL];   // fp16 intermediates
__device__ __half g_inj[(size_t)MTOT * DMODEL];
__device__ float g_segA[BATCH * NSEG * DMODEL];
__device__ float g_segB[BATCH * NSEG * DMODEL];
__device__ float g_segInit[BATCH * NSEG * DMODEL];

// ---------------- PTX helpers ----------------
__device__ __forceinline__ uint32_t s2u(const void* p) {
    return (uint32_t)__cvta_generic_to_shared(p);
}
__device__ __forceinline__ uint32_t sw128(uint32_t off) {
    return off ^ ((off >> 3) & 0x70);
}

#define MBARRIER_INIT(a, n) asm volatile("mbarrier.init.shared.b64 [%0], %1;" :: "r"(a), "r"(n) : "memory")
#define MBARRIER_EXPECT_TX(a, b) asm volatile("mbarrier.arrive.expect_tx.shared.b64 _, [%0], %1;" :: "r"(a), "r"(b) : "memory")
#define FENCE_PROXY_ASYNC() asm volatile("fence.proxy.async.shared::cta;" ::: "memory")

#define MBARRIER_WAIT_PARITY(mbar, parity) do {                               \
    uint32_t _m = (mbar); uint32_t _p = (parity); uint32_t _done;             \
    asm volatile("{\n\t.reg .pred p;\n\t"                                     \
        "mbarrier.try_wait.parity.acquire.cta.shared::cta.b64 p, [%1], %2;\n\t" \
        "selp.b32 %0, 1, 0, p;\n\t}"                                          \
        : "=r"(_done) : "r"(_m), "r"(_p) : "memory");                         \
    if (!_done) {                                                             \
        asm volatile("{\n\t.reg .pred P1;\n\t"                                \
            "WL_%=:\n\t"                                                      \
            "mbarrier.try_wait.parity.acquire.cta.shared::cta.b64 P1, [%0], %1, 0x989680;\n\t" \
            "@P1 bra.uni WD_%=;\n\t"                                          \
            "bra.uni WL_%=;\n\t"                                              \
            "WD_%=:\n\t}" :: "r"(_m), "r"(_p) : "memory");                    \
    }                                                                         \
} while (0)

__device__ __forceinline__ void tma_load_2d(uint32_t smem_addr, const CUtensorMap* tmap,
                                            int cx, int cy, uint32_t mbar) {
    asm volatile(
        "cp.async.bulk.tensor.2d.shared::cta.global.tile.mbarrier::complete_tx::bytes "
        "[%0], [%1, {%2, %3}], [%4];"
        :: "r"(smem_addr), "l"(tmap), "r"(cx), "r"(cy), "r"(mbar) : "memory");
}

__device__ __forceinline__ void ldsm_x4(uint32_t addr, uint32_t& r0, uint32_t& r1,
                                        uint32_t& r2, uint32_t& r3) {
    asm volatile("ldmatrix.sync.aligned.m8n8.x4.shared.b16 {%0,%1,%2,%3}, [%4];"
                 : "=r"(r0), "=r"(r1), "=r"(r2), "=r"(r3) : "r"(addr));
}

// fp16 inputs, fp32 accumulate
__device__ __forceinline__ void mma_f32(float* c, const uint32_t* a,
                                        uint32_t b0, uint32_t b1) {
    asm volatile(
        "mma.sync.aligned.m16n8k16.row.col.f32.f16.f16.f32 "
        "{%0,%1,%2,%3}, {%4,%5,%6,%7}, {%8,%9}, {%0,%1,%2,%3};"
        : "+f"(c[0]), "+f"(c[1]), "+f"(c[2]), "+f"(c[3])
        : "r"(a[0]), "r"(a[1]), "r"(a[2]), "r"(a[3]), "r"(b0), "r"(b1));
}

// ---------------- ncu alignment no-op (keeps gemm in profiled launch slot) ----
__global__ void prof_align_kernel() {}

__global__ __launch_bounds__(256)
void convert_x_kernel(const float* __restrict__ x) {
    size_t i = (size_t)blockIdx.x * 256 + threadIdx.x;      // float4 index
    float4 v = reinterpret_cast<const float4*>(x)[i];
    __half2 uh0 = __halves2half2(__float2half_rn(v.x), __float2half_rn(v.y));
    __half2 uh1 = __halves2half2(__float2half_rn(v.z), __float2half_rn(v.w));
    reinterpret_cast<__half2*>(X_hi)[2 * i]     = uh0;
    reinterpret_cast<__half2*>(X_hi)[2 * i + 1] = uh1;
}

__global__ __launch_bounds__(256)
void convert_w_kernel(const float* __restrict__ Wd, const float* __restrict__ Wi) {
    size_t i = (size_t)blockIdx.x * 256 + threadIdx.x;      // float4 index, 524288
    int row = (int)(i >> 8);
    int c4  = (int)(i & 255);
    const float* src = (row < DMODEL) ? (Wd + (size_t)row * KTOT)
                                      : (Wi + (size_t)(row - DMODEL) * KTOT);
    float4 v = reinterpret_cast<const float4*>(src)[c4];
    __half2 uh0 = __halves2half2(__float2half_rn(v.x), __float2half_rn(v.y));
    __half2 uh1 = __halves2half2(__float2half_rn(v.z), __float2half_rn(v.w));
    reinterpret_cast<__half2*>(Wf_hi)[2 * i]     = uh0;
    reinterpret_cast<__half2*>(Wf_hi)[2 * i + 1] = uh1;
}

// ---------------- GEMM + gate epilogue (TMA loads, single-pass fp16) ----------
// 4 warps: 2(m) x 2(n); warp tile 64x64; K64 chunks, fragment double-buffer
// pipelined ACROSS chunk boundaries (no cold warm-up); TMA mbarrier pipeline.
__global__ __launch_bounds__(GTHREADS, 2)
void gemm_tc_kernel(const __grid_constant__ CUtensorMap tmA,
                    const __grid_constant__ CUtensorMap tmB,
                    const float* __restrict__ bd, const float* __restrict__ bi) {
    extern __shared__ char smem[];
    const uint32_t smem_u = s2u(smem);
    const int tid = threadIdx.x;
    const int wid = tid >> 5;
    const int lane = tid & 31;

    const int n0 = blockIdx.x * N_TILE;        // 0..1920
    const int m0 = blockIdx.y * M_TILE;
    const bool is_decay = (n0 < DMODEL);
    const int colbase = is_decay ? n0 : (n0 - DMODEL);
    const float* bv = is_decay ? bd : bi;

    const int warp_m = (wid & 1) * 64;         // 2 warps along M (64 rows)
    const int warp_n = (wid >> 1) * 64;        // 2 warps along N (64 cols)

    float acc[4][8][4];
#pragma unroll
    for (int mt = 0; mt < 4; ++mt)
#pragma unroll
        for (int nt = 0; nt < 8; ++nt)
#pragma unroll
            for (int q = 0; q < 4; ++q) acc[mt][nt][q] = 0.0f;

    // ldmatrix lane addressing (byte columns within 128B SW128 rows)
    const int a_r = lane & 15;
    const int a_cb = (lane >> 4) * 16;         // 0 or 16 bytes
    const int b_quad = lane >> 3;
    const int b_r = lane & 7;
    const int b_row_off = ((b_quad >> 1) * 8) + b_r;
    const int b_kb = (b_quad & 1) * 16;        // 0 or 16 bytes

    uint32_t ah[2][4][4];                      // [buf][mt][reg]
    uint32_t bh[2][4][4];                      // [buf][ng][reg]

    // kcb = byte column of the k16 slice within the 128B row (0,32,64,96)
#define LOAD_FRAGS(buf, base, kcb)                                             \
    do {                                                                       \
        _Pragma("unroll")                                                      \
        for (int mt = 0; mt < 4; ++mt) {                                       \
            uint32_t bo = (uint32_t)((warp_m + mt * 16 + a_r) * ROW_BYTES + (kcb) + a_cb); \
            ldsm_x4((base) + OFF_A + sw128(bo), ah[buf][mt][0], ah[buf][mt][1],\
                    ah[buf][mt][2], ah[buf][mt][3]);                           \
        }                                                                      \
        _Pragma("unroll")                                                      \
        for (int ng = 0; ng < 4; ++ng) {                                       \
            uint32_t bo = (uint32_t)((warp_n + ng * 16 + b_row_off) * ROW_BYTES + (kcb) + b_kb); \
            ldsm_x4((base) + OFF_B + sw128(bo), bh[buf][ng][0], bh[buf][ng][1],\
                    bh[buf][ng][2], bh[buf][ng][3]);                           \
        }                                                                      \
    } while (0)

#define MMA_FRAGS(buf)                                                         \
    do {                                                                       \
        _Pragma("unroll")                                                      \
        for (int ng = 0; ng < 4; ++ng)                                         \
            _Pragma("unroll")                                                  \
            for (int mt = 0; mt < 4; ++mt) {                                   \
                mma_f32(acc[mt][2 * ng + 0], ah[buf][mt], bh[buf][ng][0], bh[buf][ng][1]); \
                mma_f32(acc[mt][2 * ng + 1], ah[buf][mt], bh[buf][ng][2], bh[buf][ng][3]); \
            }                                                                  \
    } while (0)

    // ---- mbarrier + TMA prologue ----
    const uint32_t mbar0 = smem_u + MBAR_OFF;
    if (tid == 0) {
        MBARRIER_INIT(mbar0 + 0, 1);
        MBARRIER_INIT(mbar0 + 8, 1);
        MBARRIER_INIT(mbar0 + 16, 1);
        FENCE_PROXY_ASYNC();
    }
    __syncthreads();
    if (tid == 0) {
#pragma unroll
        for (int c = 0; c < 2; ++c) {
            const uint32_t sb = smem_u + c * STAGE_BYTES;
            MBARRIER_EXPECT_TX(mbar0 + c * 8, STAGE_BYTES);
            tma_load_2d(sb + OFF_A, &tmA, c * K_CHUNK, m0, mbar0 + c * 8);
            tma_load_2d(sb + OFF_B, &tmB, c * K_CHUNK, n0, mbar0 + c * 8);
        }
    }

    int ph[NSTAGE] = {0, 0, 0};
    int st = 0;
    // warm-up: wait chunk 0, load its first fragments once
    MBARRIER_WAIT_PARITY(mbar0 + 0, ph[0]);    // non-flipping peek; flipped below
    LOAD_FRAGS(0, smem_u + 0 * STAGE_BYTES, 0);

    for (int c = 0; c < N_CHUNKS; ++c) {
        __syncthreads();                       // all warps done reading stage c-1
        if (tid == 0 && c + 2 < N_CHUNKS) {    // refill stage (c+2)%3
            int wst = st + 2; if (wst >= NSTAGE) wst -= NSTAGE;
            const uint32_t sb = smem_u + wst * STAGE_BYTES;
            MBARRIER_EXPECT_TX(mbar0 + wst * 8, STAGE_BYTES);
            tma_load_2d(sb + OFF_A, &tmA, (c + 2) * K_CHUNK, m0, mbar0 + wst * 8);
            tma_load_2d(sb + OFF_B, &tmB, (c + 2) * K_CHUNK, n0, mbar0 + wst * 8);
        }
        // consuming wait for chunk c (idempotent if already peeked) + flip
        MBARRIER_WAIT_PARITY(mbar0 + st * 8, ph[st]);
        ph[st] ^= 1;

        const uint32_t base = smem_u + st * STAGE_BYTES;
        int nst = st + 1; if (nst == NSTAGE) nst = 0;
        const uint32_t nbase = smem_u + nst * STAGE_BYTES;

        // seamless schedule: L1|M0; L2|M1; L3|M2; Lnext0|M3
        LOAD_FRAGS(1, base, 32);
        MMA_FRAGS(0);
        LOAD_FRAGS(0, base, 64);
        MMA_FRAGS(1);
        LOAD_FRAGS(1, base, 96);
        MMA_FRAGS(0);
        if (c + 1 < N_CHUNKS) {
            // peek-wait (non-flipping): chunk c+1 TMA was issued >=1 chunk ago
            MBARRIER_WAIT_PARITY(mbar0 + nst * 8, ph[nst]);
            LOAD_FRAGS(0, nbase, 0);
        }
        MMA_FRAGS(1);

        ++st; if (st == NSTAGE) st = 0;
    }

    // ---- epilogue: bias (+sigmoid), fp16 half2 stores ----
    __half* dst = is_decay ? g_decays : g_inj;
#pragma unroll
    for (int mt = 0; mt < 4; ++mt) {
        int row0 = m0 + warp_m + mt * 16 + (lane >> 2);
#pragma unroll
        for (int nt = 0; nt < 8; ++nt) {
            int gcol = colbase + warp_n + nt * 8 + (lane & 3) * 2;
            float2 bias2 = *reinterpret_cast<const float2*>(bv + gcol);
            float v0 = acc[mt][nt][0] + bias2.x;
            float v1 = acc[mt][nt][1] + bias2.y;
            float v2 = acc[mt][nt][2] + bias2.x;
            float v3 = acc[mt][nt][3] + bias2.y;
            if (is_decay) {
                v0 = __fdividef(1.0f, 1.0f + __expf(-v0));
                v1 = __fdividef(1.0f, 1.0f + __expf(-v1));
                v2 = __fdividef(1.0f, 1.0f + __expf(-v2));
                v3 = __fdividef(1.0f, 1.0f + __expf(-v3));
            }
            *reinterpret_cast<__half2*>(dst + (size_t)row0 * DMODEL + gcol) =
                __floats2half2_rn(v0, v1);
            *reinterpret_cast<__half2*>(dst + (size_t)(row0 + 8) * DMODEL + gcol) =
                __floats2half2_rn(v2, v3);
        }
    }
#undef LOAD_FRAGS
#undef MMA_FRAGS
}

// ---------------- segmented scan (fp16 in, 2 channels per thread) -------------
__global__ __launch_bounds__(256)
void scan_pass1() {
    const int g = blockIdx.x * 256 + threadIdx.x;      // 0..65535
    const int ep = g & (HALF_D - 1);                   // half2 lane (2 channels)
    const int bs = g >> 9;                             // b*NSEG + seg
    const int seg = bs & (NSEG - 1);
    const int b = bs >> 4;
    size_t p = ((size_t)b * SEQ + (size_t)seg * SEGLEN) * HALF_D + ep;
    const __half2* dh = reinterpret_cast<const __half2*>(g_decays);
    const __half2* vh = reinterpret_cast<const __half2*>(g_inj);

    float s0 = 0.0f, s1 = 0.0f, A0 = 1.0f, A1 = 1.0f;
    for (int t = 0; t < SEGLEN; t += 8) {
        float2 d[8], v[8];
#pragma unroll
        for (int j = 0; j < 8; ++j) {
            d[j] = __half22float2(dh[p + (size_t)j * HALF_D]);
            v[j] = __half22float2(vh[p + (size_t)j * HALF_D]);
        }
#pragma unroll
        for (int j = 0; j < 8; ++j) {
            s0 = fmaf(d[j].x, s0, v[j].x);  A0 *= d[j].x;
            s1 = fmaf(d[j].y, s1, v[j].y);  A1 *= d[j].y;
        }
        p += (size_t)8 * HALF_D;
    }
    const int idx = (bs << 10) | (ep * 2);
    g_segA[idx]     = A0;  g_segA[idx + 1] = A1;
    g_segB[idx]     = s0;  g_segB[idx + 1] = s1;
}

__global__ __launch_bounds__(256)
void scan_pass2() {
    const int g = blockIdx.x * 256 + threadIdx.x;      // 0..8191
    const int e = g & (DMODEL - 1);
    const int b = g >> 10;
    float s = 0.0f;
#pragma unroll
    for (int seg = 0; seg < NSEG; ++seg) {
        int idx = ((b * NSEG + seg) << 10) | e;
        g_segInit[idx] = s;
        s = fmaf(g_segA[idx], s, g_segB[idx]);
    }
}

__global__ __launch_bounds__(256)
void scan_pass3(float* __restrict__ out) {
    const int g = blockIdx.x * 256 + threadIdx.x;      // 0..65535
    const int ep = g & (HALF_D - 1);
    const int bs = g >> 9;
    const int seg = bs & (NSEG - 1);
    const int b = bs >> 4;
    size_t p = ((size_t)b * SEQ + (size_t)seg * SEGLEN) * HALF_D + ep;
    const __half2* dh = reinterpret_cast<const __half2*>(g_decays);
    const __half2* vh = reinterpret_cast<const __half2*>(g_inj);
    const int idx = (bs << 10) | (ep * 2);
    float s0 = g_segInit[idx];
    float s1 = g_segInit[idx + 1];
    size_t q = ((size_t)b * SEQ + (size_t)seg * SEGLEN) * DMODEL + ep * 2;

    for (int t = 0; t < SEGLEN; t += 8) {
        float2 d[8], v[8];
#pragma unroll
        for (int j = 0; j < 8; ++j) {
            d[j] = __half22float2(dh[p + (size_t)j * HALF_D]);
            v[j] = __half22float2(vh[p + (size_t)j * HALF_D]);
        }
#pragma unroll
        for (int j = 0; j < 8; ++j) {
            s0 = fmaf(d[j].x, s0, v[j].x);
            s1 = fmaf(d[j].y, s1, v[j].y);
            *reinterpret_cast<float2*>(out + q + (size_t)j * DMODEL) =
                make_float2(s0, s1);
        }
        p += (size_t)8 * HALF_D;
        q += (size_t)8 * DMODEL;
    }
}

// ---------------- host: tensormap construction ----------------
typedef CUresult (*PFN_cuTensorMapEncodeTiled_t)(
    CUtensorMap*, CUtensorMapDataType, cuuint32_t, void*,
    const cuuint64_t*, const cuuint64_t*, const cuuint32_t*, const cuuint32_t*,
    CUtensorMapInterleave, CUtensorMapSwizzle, CUtensorMapL2promotion,
    CUtensorMapFloatOOBfill);

static void build_tmap(PFN_cuTensorMapEncodeTiled_t enc, CUtensorMap* tm,
                       void* ptr, uint64_t rows) {
    cuuint64_t dims[2]    = {(cuuint64_t)KTOT, (cuuint64_t)rows};
    cuuint64_t strides[1] = {(cuuint64_t)KTOT * 2};
    cuuint32_t box[2]     = {K_CHUNK, 128};
    cuuint32_t estr[2]    = {1, 1};
    enc(tm, CU_TENSOR_MAP_DATA_TYPE_FLOAT16, 2, ptr, dims, strides, box, estr,
        CU_TENSOR_MAP_INTERLEAVE_NONE, CU_TENSOR_MAP_SWIZZLE_128B,
        CU_TENSOR_MAP_L2_PROMOTION_L2_128B, CU_TENSOR_MAP_FLOAT_OOB_FILL_NONE);
}

// ---------------- launch ----------------
extern "C" void kernel_launch(void* const* d_in, const int* in_sizes, int n_in,
                              void* d_out, int out_size) {
    const float* x_seq   = (const float*)d_in[0];
    const float* W_decay = (const float*)d_in[1];
    const float* b_decay = (const float*)d_in[2];
    const float* W_input = (const float*)d_in[3];
    const float* b_input = (const float*)d_in[4];
    float* out = (float*)d_out;

    static bool init_done = false;
    static CUtensorMap tmA, tmB;
    if (!init_done) {
        cudaFuncSetAttribute(gemm_tc_kernel,
                             cudaFuncAttributeMaxDynamicSharedMemorySize, SMEM_TOTAL);
        PFN_cuTensorMapEncodeTiled_t enc = nullptr;
        cudaDriverEntryPointQueryResult qres;
        cudaGetDriverEntryPoint("cuTensorMapEncodeTiled", (void**)&enc,
                                cudaEnableDefault, &qres);
        void *pX = nullptr, *pW = nullptr;
        cudaGetSymbolAddress(&pX, X_hi);
        cudaGetSymbolAddress(&pW, Wf_hi);
        build_tmap(enc, &tmA, pX, MTOT);
        build_tmap(enc, &tmB, pW, NTOT);
        init_done = true;
    }

    // keep gemm_tc_kernel in the same ncu capture slot
    prof_align_kernel<<<1, 32>>>();

    convert_x_kernel<<<(MTOT * KTOT / 4) / 256, 256>>>(x_seq);
    convert_w_kernel<<<(NTOT * KTOT / 4) / 256, 256>>>(W_decay, W_input);

    dim3 grid(NTOT / N_TILE, MTOT / M_TILE);   // (16, 256): n fastest -> A reuse in L2
    gemm_tc_kernel<<<grid, GTHREADS, SMEM_TOTAL>>>(tmA, tmB, b_decay, b_input);

    scan_pass1<<<(BATCH * NSEG * HALF_D) / 256, 256>>>();
    scan_pass2<<<(BATCH * DMODEL) / 256, 256>>>();
    scan_pass3<<<(BATCH * NSEG * HALF_D) / 256, 256>>>(out);
}